// round 13
// baseline (speedup 1.0000x reference)
#include <cuda_runtime.h>
#include <cuda_bf16.h>
#include <cuda_fp16.h>
#include <cstdint>

#define BB 256
#define TENC 512
#define TDEC 64
#define TT (TENC + TDEC)
#define DD 64
#define HH 512
#define OO 512
#define G4 2048            // 4*H
#define KHX 576            // H + D
#define OUT_OFS ((size_t)BB * TDEC * OO)

// smem layout (dynamic), bytes:
//  W @ 0          : 128 rows x 1168 B = 149504
//  A chunks @ 149504 : 9 x 4608 (32 rows x 144B)  -> 190976
//  zA @ 190976 (32x132 f32 = 16896); zB @ 207872 -> 224768
#define ABASE   149504u
#define ACH     4608u
#define ZOFS    190976u
#define SMEM_DYN 224768

// ---------------- device-global scratch ----------------
__device__ __align__(16) __half g_W[2][G4 * KHX];
__device__ __align__(16) float  g_bias[2][G4];
__device__ __align__(16) __half g_x[TT * BB * DD];
__device__ __align__(16) __half g_h[2][BB * HH];
__device__ __align__(16) __nv_bfloat16 g_Wo_hi[OO * HH];
__device__ __align__(16) __nv_bfloat16 g_Wo_lo[OO * HH];
__device__ unsigned g_cnt[8];   // per batch-group arrival counter

// ---------------- helpers ----------------
__device__ __forceinline__ void mma_f16(float (&c)[4],
                                        uint32_t a0, uint32_t a1, uint32_t a2, uint32_t a3,
                                        uint32_t b0, uint32_t b1) {
    asm volatile(
        "mma.sync.aligned.m16n8k16.row.col.f32.f16.f16.f32 "
        "{%0,%1,%2,%3}, {%4,%5,%6,%7}, {%8,%9}, {%0,%1,%2,%3};\n"
        : "+f"(c[0]), "+f"(c[1]), "+f"(c[2]), "+f"(c[3])
        : "r"(a0), "r"(a1), "r"(a2), "r"(a3), "r"(b0), "r"(b1));
}

__device__ __forceinline__ void mma_bf16(float (&c)[4],
                                         uint32_t a0, uint32_t a1, uint32_t a2, uint32_t a3,
                                         uint32_t b0, uint32_t b1) {
    asm volatile(
        "mma.sync.aligned.m16n8k16.row.col.f32.bf16.bf16.f32 "
        "{%0,%1,%2,%3}, {%4,%5,%6,%7}, {%8,%9}, {%0,%1,%2,%3};\n"
        : "+f"(c[0]), "+f"(c[1]), "+f"(c[2]), "+f"(c[3])
        : "r"(a0), "r"(a1), "r"(a2), "r"(a3), "r"(b0), "r"(b1));
}

__device__ __forceinline__ void ldsm4(uint32_t* r, uint32_t addr) {
    asm volatile("ldmatrix.sync.aligned.m8n8.x4.shared.b16 {%0,%1,%2,%3}, [%4];\n"
                 : "=r"(r[0]), "=r"(r[1]), "=r"(r[2]), "=r"(r[3]) : "r"(addr));
}

__device__ __forceinline__ void cp16(uint32_t dst, const void* src) {
    asm volatile("cp.async.cg.shared.global [%0], [%1], 16;\n" :: "r"(dst), "l"(src));
}
__device__ __forceinline__ void cp_commit() { asm volatile("cp.async.commit_group;\n"); }
template <int N> __device__ __forceinline__ void cp_wait() {
    asm volatile("cp.async.wait_group %0;\n" :: "n"(N));
}

__device__ __forceinline__ float sigmoidf_(float x) { return 1.f / (1.f + __expf(-x)); }
__device__ __forceinline__ float tanhf_(float x) { return 1.f - 2.f / (__expf(2.f * x) + 1.f); }

// ---------------- prep kernels ----------------
__global__ void prep_weights(const float* __restrict__ eWih, const float* __restrict__ eWhh,
                             const float* __restrict__ ebih, const float* __restrict__ ebhh,
                             const float* __restrict__ dWih, const float* __restrict__ dWhh,
                             const float* __restrict__ dbih, const float* __restrict__ dbhh,
                             const float* __restrict__ outW) {
    int idx = blockIdx.x * blockDim.x + threadIdx.x;
    int stride = gridDim.x * blockDim.x;
    for (int i = idx; i < 2 * G4 * KHX; i += stride) {
        int sel = i / (G4 * KHX);
        int r = i - sel * (G4 * KHX);
        int jr = r / KHX;
        int k = r - jr * KHX;
        int gate = jr & 3, col = jr >> 2;
        int js = gate * HH + col;
        const float* Wih = sel ? dWih : eWih;
        const float* Whh = sel ? dWhh : eWhh;
        float w = (k < HH) ? Whh[js * HH + k] : Wih[js * DD + (k - HH)];
        g_W[sel][jr * KHX + k] = __float2half(w);
    }
    for (int i = idx; i < 2 * G4; i += stride) {
        int sel = i >> 11;
        int jr = i & (G4 - 1);
        int gate = jr & 3, col = jr >> 2;
        int js = gate * HH + col;
        g_bias[sel][jr] = sel ? (dbih[js] + dbhh[js]) : (ebih[js] + ebhh[js]);
    }
    for (int i = idx; i < OO * HH; i += stride) {
        float w = outW[i];
        __nv_bfloat16 hi = __float2bfloat16(w);
        g_Wo_hi[i] = hi;
        g_Wo_lo[i] = __float2bfloat16(w - __bfloat162float(hi));
    }
}

__global__ void prep_x(const float* __restrict__ enc, const float* __restrict__ dec) {
    int idx = blockIdx.x * blockDim.x + threadIdx.x;
    int stride = gridDim.x * blockDim.x;
    const int total = TT * BB * DD;
    for (int i = idx; i < total; i += stride) {
        int t = i / (BB * DD);
        int r = i - t * (BB * DD);
        int b = r / DD;
        int d = r - b * DD;
        float v = (t < TENC) ? enc[(b * TENC + t) * DD + d]
                             : dec[(b * TDEC + (t - TENC)) * DD + d];
        g_x[i] = __float2half(v);
    }
}

__global__ void init_state() {
    int idx = blockIdx.x * blockDim.x + threadIdx.x;
    int stride = gridDim.x * blockDim.x;
    if (idx < 8) g_cnt[idx] = 0u;
    for (int i = idx; i < BB * HH; i += stride) {
        g_h[0][i] = __float2half(0.f);
        g_h[1][i] = __float2half(0.f);
    }
}

// ---------------- persistent LSTM kernel ----------------
// grid (16 j-blocks, 8 batch-groups) = 128 CTAs; 512 threads = 16 warps: nw4 x kw4.
// CTA tile per step: M=32 batch x N=128 gate-rows x K=576 (8 h-chunks of 64 + 1 x-chunk).
// Each warp computes FULL m32 x n32 over a k16 slice per chunk: B fragments read 1x
// (was 2x), 4 ldsm4 per warp per chunk (was 6), 8 independent accumulator chains.
__global__ __launch_bounds__(512, 1) void lstm_persist(float* __restrict__ hid_base) {
    extern __shared__ __align__(16) char sm[];
    const uint32_t sbase = (uint32_t)__cvta_generic_to_shared(sm);
    const int tid = threadIdx.x;
    const int lane = tid & 31;
    const int warp = tid >> 5;
    const int nw = warp & 3;          // n32 slice
    const int kw = warp >> 2;         // k16-of-64 slice within each chunk
    const int jb = blockIdx.x;
    const int j0 = jb * 128;          // gate-row base
    const int b0 = blockIdx.y * 32;   // batch base
    const int gm = blockIdx.y;        // batch group
    const int c0 = jb * 32;           // h-column base

    auto loadW = [&](int sel) {
        for (int j = 0; j < 18; ++j) {
            int i = tid + j * 512;
            int r = i / 72, u = i - r * 72;
            cp16(sbase + r * 1168 + u * 16, g_W[sel] + (j0 + r) * KHX + u * 8);
        }
        cp_commit();
        cp_wait<0>();
        __syncthreads();
    };
    loadW(0);

    float creg[2] = {0.f, 0.f};

    const int fr = lane & 15;
    const int fhalf = (lane >> 4) * 16;

    auto issueX = [&](int tt) {
        if (tid < 256) {
            int r = tid >> 3, u = tid & 7;
            cp16(sbase + ABASE + 8 * ACH + r * 144 + u * 16,
                 g_x + (size_t)tt * (BB * DD) + (b0 + r) * DD + u * 8);
        }
    };
    auto issueH = [&](int p) {
#pragma unroll
        for (int j = 0; j < 4; ++j) {
            int i = tid + j * 512;
            int c = i >> 8, rem = i & 255;
            int r = rem >> 3, u = rem & 7;
            cp16(sbase + ABASE + (uint32_t)(c * ACH) + r * 144 + u * 16,
                 g_h[p] + (b0 + r) * HH + c * 64 + u * 8);
        }
    };

    // acc[mi][f]: mi = m16 half (rows mi*16..), f = n8 tile within n32
    auto compute = [&](int c, float (&acc)[2][4][4]) {
        uint32_t st = sbase + ABASE + (uint32_t)(c * ACH);
        uint32_t a[8], b[8];
        uint32_t aaddr = st + fr * 144 + kw * 32 + fhalf;
        ldsm4(a, aaddr);
        ldsm4(a + 4, aaddr + 16 * 144);
        uint32_t kb = (uint32_t)(c * 128 + kw * 32) + fhalf;
        ldsm4(b,     sbase + (nw * 32 + fr) * 1168 + kb);
        ldsm4(b + 4, sbase + (nw * 32 + 16 + fr) * 1168 + kb);
#pragma unroll
        for (int mi = 0; mi < 2; ++mi)
#pragma unroll
            for (int f = 0; f < 4; ++f) {
                uint32_t b0r = b[(f >> 1) * 4 + (f & 1)];
                uint32_t b1r = b[(f >> 1) * 4 + 2 + (f & 1)];
                mma_f16(acc[mi][f], a[mi * 4], a[mi * 4 + 1], a[mi * 4 + 2],
                        a[mi * 4 + 3], b0r, b1r);
            }
    };

    float acc[2][4][4];

    // prefetch x chunk for t=0
    issueX(0);
    cp_commit();

    for (int t = 0; t < TT; ++t) {
        const int p = t & 1;
        const int sel = (t >= TENC);

        // ---- group barrier: all 16 producers published h of step t-1 ----
        if (t > 0) {
            if (tid == 0) {
                const unsigned target = 16u * (unsigned)t;
                unsigned v;
                do {
                    asm volatile("ld.acquire.gpu.global.u32 %0, [%1];"
                                 : "=r"(v) : "l"(&g_cnt[gm]));
                } while (v < target);
            }
            __syncthreads();
        }
        if (t == TENC) loadW(1);

        // ---- issue full h wave (one group) ----
        issueH(p);
        cp_commit();

#pragma unroll
        for (int mi = 0; mi < 2; ++mi)
#pragma unroll
            for (int f = 0; f < 4; ++f)
#pragma unroll
                for (int e = 0; e < 4; ++e) acc[mi][f][e] = 0.f;

        // ---- compute x chunk while h flies ----
        cp_wait<1>();
        __syncthreads();
        compute(8, acc);

        cp_wait<0>();
        __syncthreads();
#pragma unroll
        for (int c = 0; c < 8; ++c) compute(c, acc);

        // ---- kw reduction: kw even write zA/zB, kw odd add (2 rounds) ----
        float* zA = (float*)(sm + ZOFS);
        float* zB = zA + 4224;
        float* zt = (kw >> 1) ? zB : zA;   // kw0,1 -> zA ; kw2,3 -> zB
#pragma unroll
        for (int rnd = 0; rnd < 2; ++rnd) {
            if ((kw & 1) == rnd) {
#pragma unroll
                for (int mi = 0; mi < 2; ++mi)
#pragma unroll
                    for (int f = 0; f < 4; ++f) {
                        int zr = mi * 16 + (lane >> 2);
                        int zc = nw * 32 + f * 8 + (lane & 3) * 2;
                        if (rnd == 0) {
                            zt[zr * 132 + zc]           = acc[mi][f][0];
                            zt[zr * 132 + zc + 1]       = acc[mi][f][1];
                            zt[(zr + 8) * 132 + zc]     = acc[mi][f][2];
                            zt[(zr + 8) * 132 + zc + 1] = acc[mi][f][3];
                        } else {
                            zt[zr * 132 + zc]           += acc[mi][f][0];
                            zt[zr * 132 + zc + 1]       += acc[mi][f][1];
                            zt[(zr + 8) * 132 + zc]     += acc[mi][f][2];
                            zt[(zr + 8) * 132 + zc + 1] += acc[mi][f][3];
                        }
                    }
            }
            __syncthreads();
        }

        // ---- LSTM cell epilogue (c in registers) ----
        const float* bias = g_bias[sel] + j0;
        const int wp = p ^ 1;
        float hN2[2];
#pragma unroll
        for (int it = 0; it < 2; ++it) {
            int e = tid + it * 512;
            int bl_ = e >> 5, cl = e & 31;
            float zi = zA[bl_ * 132 + cl * 4 + 0] + zB[bl_ * 132 + cl * 4 + 0] + bias[cl * 4 + 0];
            float zf = zA[bl_ * 132 + cl * 4 + 1] + zB[bl_ * 132 + cl * 4 + 1] + bias[cl * 4 + 1];
            float zg = zA[bl_ * 132 + cl * 4 + 2] + zB[bl_ * 132 + cl * 4 + 2] + bias[cl * 4 + 2];
            float zo = zA[bl_ * 132 + cl * 4 + 3] + zB[bl_ * 132 + cl * 4 + 3] + bias[cl * 4 + 3];
            float ig = sigmoidf_(zi);
            float fg = sigmoidf_(zf);
            float gg = tanhf_(zg);
            float og = sigmoidf_(zo);
            float cN = fg * creg[it] + ig * gg;
            float hN = og * tanhf_(cN);
            creg[it] = cN;
            hN2[it] = hN;
            g_h[wp][(b0 + bl_) * HH + c0 + cl] = __float2half(hN);
        }
        __syncthreads();   // all h stores done before the release arrival

        if (t + 1 < TT) {
            if (tid == 0) {
                asm volatile("red.release.gpu.global.add.u32 [%0], %1;"
                             :: "l"(&g_cnt[gm]), "r"(1u) : "memory");
            }
            issueX(t + 1);            // next-step x into slot 8
            cp_commit();
        }
        if (t >= TENC) {
#pragma unroll
            for (int it = 0; it < 2; ++it) {
                int e = tid + it * 512;
                int bl_ = e >> 5, cl = e & 31;
                hid_base[(size_t)(b0 + bl_) * (TDEC * HH) + (t - TENC) * HH + c0 + cl] = hN2[it];
            }
        }
    }
}

// ---------------- final output projection (bf16 3-term) ----------------
struct STiles {
    __nv_bfloat16 Ah[2][32][36];
    __nv_bfloat16 Al[2][32][36];
    __nv_bfloat16 Bh[2][128][36];
    __nv_bfloat16 Bl[2][128][36];
};
union SU {
    STiles t;
    float z[32][132];
};

__global__ __launch_bounds__(256) void proj_kernel(const float* __restrict__ hid,
                                                   const float* __restrict__ outb,
                                                   float* __restrict__ out) {
    __shared__ SU su;
    const int tid = threadIdx.x;
    const int lane = tid & 31;
    const int warp = tid >> 5;
    const int wm = (warp & 1) * 16;
    const int wn = (warp >> 1) * 32;
    const int m0 = blockIdx.y * 32;
    const int n0 = blockIdx.x * 128;

    float acc[4][4];
#pragma unroll
    for (int s = 0; s < 4; ++s)
#pragma unroll
        for (int i = 0; i < 4; ++i) acc[s][i] = 0.f;

#pragma unroll
    for (int j = 0; j < 4; ++j) {
        int i = tid + j * 256;
        int row = i >> 5, k = i & 31;
        float v = hid[(m0 + row) * HH + k];
        __nv_bfloat16 hi = __float2bfloat16(v);
        su.t.Ah[0][row][k] = hi;
        su.t.Al[0][row][k] = __float2bfloat16(v - __bfloat162float(hi));
    }
#pragma unroll
    for (int j = 0; j < 8; ++j) {
        int i = tid + j * 256;
        int row = i >> 4, k2 = (i & 15) * 2;
        int off = (n0 + row) * HH + k2;
        *(uint32_t*)&su.t.Bh[0][row][k2] = *(const uint32_t*)(g_Wo_hi + off);
        *(uint32_t*)&su.t.Bl[0][row][k2] = *(const uint32_t*)(g_Wo_lo + off);
    }

    float pv[4];
    uint32_t pBh[8], pBl[8];
    const int NCHP = HH / 32;

    for (int kc = 0; kc < NCHP; ++kc) {
        __syncthreads();
        const int q = kc & 1;
        if (kc + 1 < NCHP) {
            const int kn = kc + 1;
#pragma unroll
            for (int j = 0; j < 4; ++j) {
                int i = tid + j * 256;
                int row = i >> 5, k = i & 31;
                pv[j] = hid[(m0 + row) * HH + kn * 32 + k];
            }
#pragma unroll
            for (int j = 0; j < 8; ++j) {
                int i = tid + j * 256;
                int row = i >> 4, k2 = (i & 15) * 2;
                int off = (n0 + row) * HH + kn * 32 + k2;
                pBh[j] = *(const uint32_t*)(g_Wo_hi + off);
                pBl[j] = *(const uint32_t*)(g_Wo_lo + off);
            }
        }
#pragma unroll
        for (int k16 = 0; k16 < 2; ++k16) {
            const int ar = wm + (lane >> 2);
            const int ac = (lane & 3) * 2 + k16 * 16;
            uint32_t ah0 = *(const uint32_t*)&su.t.Ah[q][ar][ac];
            uint32_t ah1 = *(const uint32_t*)&su.t.Ah[q][ar + 8][ac];
            uint32_t ah2 = *(const uint32_t*)&su.t.Ah[q][ar][ac + 8];
            uint32_t ah3 = *(const uint32_t*)&su.t.Ah[q][ar + 8][ac + 8];
            uint32_t al0 = *(const uint32_t*)&su.t.Al[q][ar][ac];
            uint32_t al1 = *(const uint32_t*)&su.t.Al[q][ar + 8][ac];
            uint32_t al2 = *(const uint32_t*)&su.t.Al[q][ar][ac + 8];
            uint32_t al3 = *(const uint32_t*)&su.t.Al[q][ar + 8][ac + 8];
#pragma unroll
            for (int s = 0; s < 4; ++s) {
                const int br = wn + s * 8 + (lane >> 2);
                const int bc = (lane & 3) * 2 + k16 * 16;
                uint32_t bh0 = *(const uint32_t*)&su.t.Bh[q][br][bc];
                uint32_t bh1 = *(const uint32_t*)&su.t.Bh[q][br][bc + 8];
                uint32_t bl0 = *(const uint32_t*)&su.t.Bl[q][br][bc];
                uint32_t bl1 = *(const uint32_t*)&su.t.Bl[q][br][bc + 8];
                mma_bf16(acc[s], ah0, ah1, ah2, ah3, bh0, bh1);
                mma_bf16(acc[s], ah0, ah1, ah2, ah3, bl0, bl1);
                mma_bf16(acc[s], al0, al1, al2, al3, bh0, bh1);
            }
        }
        if (kc + 1 < NCHP) {
            const int qn = q ^ 1;
#pragma unroll
            for (int j = 0; j < 4; ++j) {
                int i = tid + j * 256;
                int row = i >> 5, k = i & 31;
                __nv_bfloat16 hi = __float2bfloat16(pv[j]);
                su.t.Ah[qn][row][k] = hi;
                su.t.Al[qn][row][k] = __float2bfloat16(pv[j] - __bfloat162float(hi));
            }
#pragma unroll
            for (int j = 0; j < 8; ++j) {
                int i = tid + j * 256;
                int row = i >> 4, k2 = (i & 15) * 2;
                *(uint32_t*)&su.t.Bh[qn][row][k2] = pBh[j];
                *(uint32_t*)&su.t.Bl[qn][row][k2] = pBl[j];
            }
        }
    }

#pragma unroll
    for (int s = 0; s < 4; ++s) {
        const int r = m0 + wm + (lane >> 2);
        const int cc = n0 + wn + s * 8 + (lane & 3) * 2;
        out[(size_t)r * OO + cc]           = acc[s][0] + outb[cc];
        out[(size_t)r * OO + cc + 1]       = acc[s][1] + outb[cc + 1];
        out[(size_t)(r + 8) * OO + cc]     = acc[s][2] + outb[cc];
        out[(size_t)(r + 8) * OO + cc + 1] = acc[s][3] + outb[cc + 1];
    }
}

// ---------------- launch ----------------
extern "C" void kernel_launch(void* const* d_in, const int* in_sizes, int n_in,
                              void* d_out, int out_size) {
    const float* enc_inp = (const float*)d_in[0];
    const float* dec_inp = (const float*)d_in[1];
    const float* eWih = (const float*)d_in[2];
    const float* eWhh = (const float*)d_in[3];
    const float* ebih = (const float*)d_in[4];
    const float* ebhh = (const float*)d_in[5];
    const float* dWih = (const float*)d_in[6];
    const float* dWhh = (const float*)d_in[7];
    const float* dbih = (const float*)d_in[8];
    const float* dbhh = (const float*)d_in[9];
    const float* outW = (const float*)d_in[10];
    const float* outb = (const float*)d_in[11];
    float* out = (float*)d_out;

    static int configured = 0;
    if (!configured) {
        cudaFuncSetAttribute(lstm_persist, cudaFuncAttributeMaxDynamicSharedMemorySize,
                             SMEM_DYN);
        configured = 1;
    }

    prep_weights<<<256, 256>>>(eWih, eWhh, ebih, ebhh, dWih, dWhh, dbih, dbhh, outW);
    prep_x<<<2048, 256>>>(enc_inp, dec_inp);
    init_state<<<512, 256>>>();

    float* hid_base = out + OUT_OFS;
    lstm_persist<<<dim3(16, 8), 512, SMEM_DYN>>>(hid_base);
    proj_kernel<<<dim3(4, 512), 256>>>(hid_base, outb, out);
}

// round 14
// speedup vs baseline: 1.4986x; 1.4986x over previous
#include <cuda_runtime.h>
#include <cuda_bf16.h>
#include <cuda_fp16.h>
#include <cstdint>

#define BB 256
#define TENC 512
#define TDEC 64
#define TT (TENC + TDEC)
#define DD 64
#define HH 512
#define OO 512
#define G4 2048            // 4*H
#define KHX 576            // H + D
#define OUT_OFS ((size_t)BB * TDEC * OO)

// smem layout (dynamic), bytes:
//  W @ 0          : 128 rows x 1168 B = 149504
//  A chunks @ 149504 : 9 x 4608 (32 rows x 144B)  -> 190976
//  zA @ 190976 (32x132 f32 = 16896); zB @ 207872 -> 224768
#define ABASE   149504u
#define ACH     4608u
#define ZOFS    190976u
#define SMEM_DYN 224768

// ---------------- device-global scratch ----------------
__device__ __align__(16) __half g_W[2][G4 * KHX];
__device__ __align__(16) float  g_bias[2][G4];
__device__ __align__(16) __half g_x[TT * BB * DD];
__device__ __align__(16) __half g_h[2][BB * HH];
__device__ __align__(16) __nv_bfloat16 g_Wo_hi[OO * HH];
__device__ __align__(16) __nv_bfloat16 g_Wo_lo[OO * HH];
__device__ unsigned g_flag[8][16];   // [batch-group][producer j-block] step flags

// ---------------- helpers ----------------
__device__ __forceinline__ void mma_f16(float (&c)[4],
                                        uint32_t a0, uint32_t a1, uint32_t a2, uint32_t a3,
                                        uint32_t b0, uint32_t b1) {
    asm volatile(
        "mma.sync.aligned.m16n8k16.row.col.f32.f16.f16.f32 "
        "{%0,%1,%2,%3}, {%4,%5,%6,%7}, {%8,%9}, {%0,%1,%2,%3};\n"
        : "+f"(c[0]), "+f"(c[1]), "+f"(c[2]), "+f"(c[3])
        : "r"(a0), "r"(a1), "r"(a2), "r"(a3), "r"(b0), "r"(b1));
}

__device__ __forceinline__ void mma_bf16(float (&c)[4],
                                         uint32_t a0, uint32_t a1, uint32_t a2, uint32_t a3,
                                         uint32_t b0, uint32_t b1) {
    asm volatile(
        "mma.sync.aligned.m16n8k16.row.col.f32.bf16.bf16.f32 "
        "{%0,%1,%2,%3}, {%4,%5,%6,%7}, {%8,%9}, {%0,%1,%2,%3};\n"
        : "+f"(c[0]), "+f"(c[1]), "+f"(c[2]), "+f"(c[3])
        : "r"(a0), "r"(a1), "r"(a2), "r"(a3), "r"(b0), "r"(b1));
}

__device__ __forceinline__ void ldsm4(uint32_t* r, uint32_t addr) {
    asm volatile("ldmatrix.sync.aligned.m8n8.x4.shared.b16 {%0,%1,%2,%3}, [%4];\n"
                 : "=r"(r[0]), "=r"(r[1]), "=r"(r[2]), "=r"(r[3]) : "r"(addr));
}

__device__ __forceinline__ void cp16(uint32_t dst, const void* src) {
    asm volatile("cp.async.cg.shared.global [%0], [%1], 16;\n" :: "r"(dst), "l"(src));
}
__device__ __forceinline__ void cp_commit() { asm volatile("cp.async.commit_group;\n"); }
template <int N> __device__ __forceinline__ void cp_wait() {
    asm volatile("cp.async.wait_group %0;\n" :: "n"(N));
}

__device__ __forceinline__ float sigmoidf_(float x) { return 1.f / (1.f + __expf(-x)); }
__device__ __forceinline__ float tanhf_(float x) { return 1.f - 2.f / (__expf(2.f * x) + 1.f); }

// ---------------- prep kernels ----------------
__global__ void prep_weights(const float* __restrict__ eWih, const float* __restrict__ eWhh,
                             const float* __restrict__ ebih, const float* __restrict__ ebhh,
                             const float* __restrict__ dWih, const float* __restrict__ dWhh,
                             const float* __restrict__ dbih, const float* __restrict__ dbhh,
                             const float* __restrict__ outW) {
    int idx = blockIdx.x * blockDim.x + threadIdx.x;
    int stride = gridDim.x * blockDim.x;
    for (int i = idx; i < 2 * G4 * KHX; i += stride) {
        int sel = i / (G4 * KHX);
        int r = i - sel * (G4 * KHX);
        int jr = r / KHX;
        int k = r - jr * KHX;
        int gate = jr & 3, col = jr >> 2;
        int js = gate * HH + col;
        const float* Wih = sel ? dWih : eWih;
        const float* Whh = sel ? dWhh : eWhh;
        float w = (k < HH) ? Whh[js * HH + k] : Wih[js * DD + (k - HH)];
        g_W[sel][jr * KHX + k] = __float2half(w);
    }
    for (int i = idx; i < 2 * G4; i += stride) {
        int sel = i >> 11;
        int jr = i & (G4 - 1);
        int gate = jr & 3, col = jr >> 2;
        int js = gate * HH + col;
        g_bias[sel][jr] = sel ? (dbih[js] + dbhh[js]) : (ebih[js] + ebhh[js]);
    }
    for (int i = idx; i < OO * HH; i += stride) {
        float w = outW[i];
        __nv_bfloat16 hi = __float2bfloat16(w);
        g_Wo_hi[i] = hi;
        g_Wo_lo[i] = __float2bfloat16(w - __bfloat162float(hi));
    }
}

__global__ void prep_x(const float* __restrict__ enc, const float* __restrict__ dec) {
    int idx = blockIdx.x * blockDim.x + threadIdx.x;
    int stride = gridDim.x * blockDim.x;
    const int total = TT * BB * DD;
    for (int i = idx; i < total; i += stride) {
        int t = i / (BB * DD);
        int r = i - t * (BB * DD);
        int b = r / DD;
        int d = r - b * DD;
        float v = (t < TENC) ? enc[(b * TENC + t) * DD + d]
                             : dec[(b * TDEC + (t - TENC)) * DD + d];
        g_x[i] = __float2half(v);
    }
}

__global__ void init_state() {
    int idx = blockIdx.x * blockDim.x + threadIdx.x;
    int stride = gridDim.x * blockDim.x;
    if (idx < 128) ((unsigned*)g_flag)[idx] = 0u;
    for (int i = idx; i < BB * HH; i += stride) {
        g_h[0][i] = __float2half(0.f);
        g_h[1][i] = __float2half(0.f);
    }
}

// ---------------- persistent LSTM kernel ----------------
// grid (16 j-blocks, 8 batch-groups) = 128 CTAs; 512 threads = 16 warps: nw4 x mw2 x kw2
// CTA tile per step: M=32 batch x N=128 gate-rows x K=576 (8 h-chunks of 64 + 1 x-chunk).
// Exact R8 schedule; ONLY change: per-producer flag barrier (st.release + parallel polls)
// instead of a single contended atomic counter.
__global__ __launch_bounds__(512, 1) void lstm_persist(float* __restrict__ hid_base) {
    extern __shared__ __align__(16) char sm[];
    const uint32_t sbase = (uint32_t)__cvta_generic_to_shared(sm);
    const int tid = threadIdx.x;
    const int lane = tid & 31;
    const int warp = tid >> 5;
    const int nw = warp & 3;
    const int mw = (warp >> 2) & 1;
    const int kw = warp >> 3;
    const int jb = blockIdx.x;
    const int j0 = jb * 128;          // gate-row base
    const int b0 = blockIdx.y * 32;   // batch base
    const int gm = blockIdx.y;        // batch group
    const int c0 = jb * 32;           // h-column base

    auto loadW = [&](int sel) {
        for (int j = 0; j < 18; ++j) {
            int i = tid + j * 512;
            int r = i / 72, u = i - r * 72;
            cp16(sbase + r * 1168 + u * 16, g_W[sel] + (j0 + r) * KHX + u * 8);
        }
        cp_commit();
        cp_wait<0>();
        __syncthreads();
    };
    loadW(0);

    float creg[2] = {0.f, 0.f};

    const int fr = lane & 15;
    const int fhalf = (lane >> 4) * 16;

    auto issueX = [&](int tt) {
        if (tid < 256) {
            int r = tid >> 3, u = tid & 7;
            cp16(sbase + ABASE + 8 * ACH + r * 144 + u * 16,
                 g_x + (size_t)tt * (BB * DD) + (b0 + r) * DD + u * 8);
        }
    };
    auto issueH = [&](int p) {
#pragma unroll
        for (int j = 0; j < 4; ++j) {
            int i = tid + j * 512;
            int c = i >> 8, rem = i & 255;
            int r = rem >> 3, u = rem & 7;
            cp16(sbase + ABASE + (uint32_t)(c * ACH) + r * 144 + u * 16,
                 g_h[p] + (b0 + r) * HH + c * 64 + u * 8);
        }
    };

    auto compute = [&](int c, float (&acc)[4][4]) {
        uint32_t st = sbase + ABASE + (uint32_t)(c * ACH);
#pragma unroll
        for (int ks = 0; ks < 2; ++ks) {
            uint32_t a[4], b[8];
            ldsm4(a, st + (mw * 16 + fr) * 144 + kw * 64 + ks * 32 + fhalf);
            uint32_t kb = (uint32_t)(c * 128 + kw * 64 + ks * 32) + fhalf;
            ldsm4(b,     sbase + (nw * 32 + fr) * 1168 + kb);
            ldsm4(b + 4, sbase + (nw * 32 + 16 + fr) * 1168 + kb);
#pragma unroll
            for (int f = 0; f < 4; ++f) {
                uint32_t b0r = b[(f >> 1) * 4 + (f & 1)];
                uint32_t b1r = b[(f >> 1) * 4 + 2 + (f & 1)];
                mma_f16(acc[f], a[0], a[1], a[2], a[3], b0r, b1r);
            }
        }
    };

    float acc[4][4];

    // prefetch x chunk for t=0
    issueX(0);
    cp_commit();

    for (int t = 0; t < TT; ++t) {
        const int p = t & 1;
        const int sel = (t >= TENC);

        // ---- group barrier: 16 parallel per-producer flag polls ----
        if (t > 0) {
            if (tid < 16) {
                const unsigned target = (unsigned)t;
                unsigned v;
                do {
                    asm volatile("ld.acquire.gpu.global.u32 %0, [%1];"
                                 : "=r"(v) : "l"(&g_flag[gm][tid]));
                } while (v < target);
            }
            __syncthreads();
        }
        if (t == TENC) loadW(1);

        // ---- issue full h wave (one group) ----
        issueH(p);
        cp_commit();

#pragma unroll
        for (int f = 0; f < 4; ++f)
#pragma unroll
            for (int e = 0; e < 4; ++e) acc[f][e] = 0.f;

        // ---- compute x chunk while h flies ----
        cp_wait<1>();
        __syncthreads();
        compute(8, acc);

        cp_wait<0>();
        __syncthreads();
#pragma unroll
        for (int c = 0; c < 8; ++c) compute(c, acc);

        // ---- single-round kw reduction: kw0 -> zA, kw1 -> zB concurrently ----
        float* zA = (float*)(sm + ZOFS);
        float* zB = zA + 4224;
        float* zt = kw ? zB : zA;
#pragma unroll
        for (int f = 0; f < 4; ++f) {
            int zr = mw * 16 + (lane >> 2);
            int zc = nw * 32 + f * 8 + (lane & 3) * 2;
            zt[zr * 132 + zc]           = acc[f][0];
            zt[zr * 132 + zc + 1]       = acc[f][1];
            zt[(zr + 8) * 132 + zc]     = acc[f][2];
            zt[(zr + 8) * 132 + zc + 1] = acc[f][3];
        }
        __syncthreads();

        // ---- LSTM cell epilogue (c in registers) ----
        const float* bias = g_bias[sel] + j0;
        const int wp = p ^ 1;
        float hN2[2];
#pragma unroll
        for (int it = 0; it < 2; ++it) {
            int e = tid + it * 512;
            int bl_ = e >> 5, cl = e & 31;
            float zi = zA[bl_ * 132 + cl * 4 + 0] + zB[bl_ * 132 + cl * 4 + 0] + bias[cl * 4 + 0];
            float zf = zA[bl_ * 132 + cl * 4 + 1] + zB[bl_ * 132 + cl * 4 + 1] + bias[cl * 4 + 1];
            float zg = zA[bl_ * 132 + cl * 4 + 2] + zB[bl_ * 132 + cl * 4 + 2] + bias[cl * 4 + 2];
            float zo = zA[bl_ * 132 + cl * 4 + 3] + zB[bl_ * 132 + cl * 4 + 3] + bias[cl * 4 + 3];
            float ig = sigmoidf_(zi);
            float fg = sigmoidf_(zf);
            float gg = tanhf_(zg);
            float og = sigmoidf_(zo);
            float cN = fg * creg[it] + ig * gg;
            float hN = og * tanhf_(cN);
            creg[it] = cN;
            hN2[it] = hN;
            g_h[wp][(b0 + bl_) * HH + c0 + cl] = __float2half(hN);
        }
        __syncthreads();   // all h stores done before the release store

        if (t + 1 < TT) {
            if (tid == 0) {
                asm volatile("st.release.gpu.global.u32 [%0], %1;"
                             :: "l"(&g_flag[gm][jb]), "r"((unsigned)(t + 1)) : "memory");
            }
            issueX(t + 1);            // next-step x into slot 8
            cp_commit();
        }
        if (t >= TENC) {
#pragma unroll
            for (int it = 0; it < 2; ++it) {
                int e = tid + it * 512;
                int bl_ = e >> 5, cl = e & 31;
                hid_base[(size_t)(b0 + bl_) * (TDEC * HH) + (t - TENC) * HH + c0 + cl] = hN2[it];
            }
        }
    }
}

// ---------------- final output projection (bf16 3-term) ----------------
struct STiles {
    __nv_bfloat16 Ah[2][32][36];
    __nv_bfloat16 Al[2][32][36];
    __nv_bfloat16 Bh[2][128][36];
    __nv_bfloat16 Bl[2][128][36];
};
union SU {
    STiles t;
    float z[32][132];
};

__global__ __launch_bounds__(256) void proj_kernel(const float* __restrict__ hid,
                                                   const float* __restrict__ outb,
                                                   float* __restrict__ out) {
    __shared__ SU su;
    const int tid = threadIdx.x;
    const int lane = tid & 31;
    const int warp = tid >> 5;
    const int wm = (warp & 1) * 16;
    const int wn = (warp >> 1) * 32;
    const int m0 = blockIdx.y * 32;
    const int n0 = blockIdx.x * 128;

    float acc[4][4];
#pragma unroll
    for (int s = 0; s < 4; ++s)
#pragma unroll
        for (int i = 0; i < 4; ++i) acc[s][i] = 0.f;

#pragma unroll
    for (int j = 0; j < 4; ++j) {
        int i = tid + j * 256;
        int row = i >> 5, k = i & 31;
        float v = hid[(m0 + row) * HH + k];
        __nv_bfloat16 hi = __float2bfloat16(v);
        su.t.Ah[0][row][k] = hi;
        su.t.Al[0][row][k] = __float2bfloat16(v - __bfloat162float(hi));
    }
#pragma unroll
    for (int j = 0; j < 8; ++j) {
        int i = tid + j * 256;
        int row = i >> 4, k2 = (i & 15) * 2;
        int off = (n0 + row) * HH + k2;
        *(uint32_t*)&su.t.Bh[0][row][k2] = *(const uint32_t*)(g_Wo_hi + off);
        *(uint32_t*)&su.t.Bl[0][row][k2] = *(const uint32_t*)(g_Wo_lo + off);
    }

    float pv[4];
    uint32_t pBh[8], pBl[8];
    const int NCHP = HH / 32;

    for (int kc = 0; kc < NCHP; ++kc) {
        __syncthreads();
        const int q = kc & 1;
        if (kc + 1 < NCHP) {
            const int kn = kc + 1;
#pragma unroll
            for (int j = 0; j < 4; ++j) {
                int i = tid + j * 256;
                int row = i >> 5, k = i & 31;
                pv[j] = hid[(m0 + row) * HH + kn * 32 + k];
            }
#pragma unroll
            for (int j = 0; j < 8; ++j) {
                int i = tid + j * 256;
                int row = i >> 4, k2 = (i & 15) * 2;
                int off = (n0 + row) * HH + kn * 32 + k2;
                pBh[j] = *(const uint32_t*)(g_Wo_hi + off);
                pBl[j] = *(const uint32_t*)(g_Wo_lo + off);
            }
        }
#pragma unroll
        for (int k16 = 0; k16 < 2; ++k16) {
            const int ar = wm + (lane >> 2);
            const int ac = (lane & 3) * 2 + k16 * 16;
            uint32_t ah0 = *(const uint32_t*)&su.t.Ah[q][ar][ac];
            uint32_t ah1 = *(const uint32_t*)&su.t.Ah[q][ar + 8][ac];
            uint32_t ah2 = *(const uint32_t*)&su.t.Ah[q][ar][ac + 8];
            uint32_t ah3 = *(const uint32_t*)&su.t.Ah[q][ar + 8][ac + 8];
            uint32_t al0 = *(const uint32_t*)&su.t.Al[q][ar][ac];
            uint32_t al1 = *(const uint32_t*)&su.t.Al[q][ar + 8][ac];
            uint32_t al2 = *(const uint32_t*)&su.t.Al[q][ar][ac + 8];
            uint32_t al3 = *(const uint32_t*)&su.t.Al[q][ar + 8][ac + 8];
#pragma unroll
            for (int s = 0; s < 4; ++s) {
                const int br = wn + s * 8 + (lane >> 2);
                const int bc = (lane & 3) * 2 + k16 * 16;
                uint32_t bh0 = *(const uint32_t*)&su.t.Bh[q][br][bc];
                uint32_t bh1 = *(const uint32_t*)&su.t.Bh[q][br][bc + 8];
                uint32_t bl0 = *(const uint32_t*)&su.t.Bl[q][br][bc];
                uint32_t bl1 = *(const uint32_t*)&su.t.Bl[q][br][bc + 8];
                mma_bf16(acc[s], ah0, ah1, ah2, ah3, bh0, bh1);
                mma_bf16(acc[s], ah0, ah1, ah2, ah3, bl0, bl1);
                mma_bf16(acc[s], al0, al1, al2, al3, bh0, bh1);
            }
        }
        if (kc + 1 < NCHP) {
            const int qn = q ^ 1;
#pragma unroll
            for (int j = 0; j < 4; ++j) {
                int i = tid + j * 256;
                int row = i >> 5, k = i & 31;
                __nv_bfloat16 hi = __float2bfloat16(pv[j]);
                su.t.Ah[qn][row][k] = hi;
                su.t.Al[qn][row][k] = __float2bfloat16(pv[j] - __bfloat162float(hi));
            }
#pragma unroll
            for (int j = 0; j < 8; ++j) {
                int i = tid + j * 256;
                int row = i >> 4, k2 = (i & 15) * 2;
                *(uint32_t*)&su.t.Bh[qn][row][k2] = pBh[j];
                *(uint32_t*)&su.t.Bl[qn][row][k2] = pBl[j];
            }
        }
    }

#pragma unroll
    for (int s = 0; s < 4; ++s) {
        const int r = m0 + wm + (lane >> 2);
        const int cc = n0 + wn + s * 8 + (lane & 3) * 2;
        out[(size_t)r * OO + cc]           = acc[s][0] + outb[cc];
        out[(size_t)r * OO + cc + 1]       = acc[s][1] + outb[cc + 1];
        out[(size_t)(r + 8) * OO + cc]     = acc[s][2] + outb[cc];
        out[(size_t)(r + 8) * OO + cc + 1] = acc[s][3] + outb[cc + 1];
    }
}

// ---------------- launch ----------------
extern "C" void kernel_launch(void* const* d_in, const int* in_sizes, int n_in,
                              void* d_out, int out_size) {
    const float* enc_inp = (const float*)d_in[0];
    const float* dec_inp = (const float*)d_in[1];
    const float* eWih = (const float*)d_in[2];
    const float* eWhh = (const float*)d_in[3];
    const float* ebih = (const float*)d_in[4];
    const float* ebhh = (const float*)d_in[5];
    const float* dWih = (const float*)d_in[6];
    const float* dWhh = (const float*)d_in[7];
    const float* dbih = (const float*)d_in[8];
    const float* dbhh = (const float*)d_in[9];
    const float* outW = (const float*)d_in[10];
    const float* outb = (const float*)d_in[11];
    float* out = (float*)d_out;

    static int configured = 0;
    if (!configured) {
        cudaFuncSetAttribute(lstm_persist, cudaFuncAttributeMaxDynamicSharedMemorySize,
                             SMEM_DYN);
        configured = 1;
    }

    prep_weights<<<256, 256>>>(eWih, eWhh, ebih, ebhh, dWih, dWhh, dbih, dbhh, outW);
    prep_x<<<2048, 256>>>(enc_inp, dec_inp);
    init_state<<<512, 256>>>();

    float* hid_base = out + OUT_OFS;
    lstm_persist<<<dim3(16, 8), 512, SMEM_DYN>>>(hid_base);
    proj_kernel<<<dim3(4, 512), 256>>>(hid_base, outb, out);
}

// round 15
// speedup vs baseline: 1.5695x; 1.0473x over previous
#include <cuda_runtime.h>
#include <cuda_bf16.h>
#include <cuda_fp16.h>
#include <cstdint>

#define BB 256
#define TENC 512
#define TDEC 64
#define TT (TENC + TDEC)
#define DD 64
#define HH 512
#define OO 512
#define G4 2048            // 4*H
#define KHX 576            // H + D
#define OUT_OFS ((size_t)BB * TDEC * OO)

// smem layout (dynamic), bytes:
//  W @ 0          : 128 rows x 1168 B = 149504
//  A chunks @ 149504 : 9 x 4608 (32 rows x 144B)  -> 190976
//  zA @ 190976 (32x132 f32 = 16896); zB @ 207872 -> 224768
#define ABASE   149504u
#define ACH     4608u
#define ZOFS    190976u
#define SMEM_DYN 224768

// ---------------- device-global scratch ----------------
__device__ __align__(16) __half g_W[2][G4 * KHX];
__device__ __align__(16) float  g_bias[2][G4];
__device__ __align__(16) __half g_x[TT * BB * DD];
__device__ __align__(16) __half g_h[2][BB * HH];
__device__ __align__(16) __nv_bfloat16 g_Wo_hi[OO * HH];
__device__ __align__(16) __nv_bfloat16 g_Wo_lo[OO * HH];
__device__ unsigned g_cnt[8];   // per batch-group arrival counter

// ---------------- helpers ----------------
__device__ __forceinline__ void mma_f16(float (&c)[4],
                                        uint32_t a0, uint32_t a1, uint32_t a2, uint32_t a3,
                                        uint32_t b0, uint32_t b1) {
    asm volatile(
        "mma.sync.aligned.m16n8k16.row.col.f32.f16.f16.f32 "
        "{%0,%1,%2,%3}, {%4,%5,%6,%7}, {%8,%9}, {%0,%1,%2,%3};\n"
        : "+f"(c[0]), "+f"(c[1]), "+f"(c[2]), "+f"(c[3])
        : "r"(a0), "r"(a1), "r"(a2), "r"(a3), "r"(b0), "r"(b1));
}

__device__ __forceinline__ void mma_bf16(float (&c)[4],
                                         uint32_t a0, uint32_t a1, uint32_t a2, uint32_t a3,
                                         uint32_t b0, uint32_t b1) {
    asm volatile(
        "mma.sync.aligned.m16n8k16.row.col.f32.bf16.bf16.f32 "
        "{%0,%1,%2,%3}, {%4,%5,%6,%7}, {%8,%9}, {%0,%1,%2,%3};\n"
        : "+f"(c[0]), "+f"(c[1]), "+f"(c[2]), "+f"(c[3])
        : "r"(a0), "r"(a1), "r"(a2), "r"(a3), "r"(b0), "r"(b1));
}

__device__ __forceinline__ void ldsm4(uint32_t* r, uint32_t addr) {
    asm volatile("ldmatrix.sync.aligned.m8n8.x4.shared.b16 {%0,%1,%2,%3}, [%4];\n"
                 : "=r"(r[0]), "=r"(r[1]), "=r"(r[2]), "=r"(r[3]) : "r"(addr));
}

__device__ __forceinline__ void cp16(uint32_t dst, const void* src) {
    asm volatile("cp.async.cg.shared.global [%0], [%1], 16;\n" :: "r"(dst), "l"(src));
}
__device__ __forceinline__ void cp_commit() { asm volatile("cp.async.commit_group;\n"); }
template <int N> __device__ __forceinline__ void cp_wait() {
    asm volatile("cp.async.wait_group %0;\n" :: "n"(N));
}

__device__ __forceinline__ float sigmoidf_(float x) { return 1.f / (1.f + __expf(-x)); }
__device__ __forceinline__ float tanhf_(float x) { return 1.f - 2.f / (__expf(2.f * x) + 1.f); }

// ---------------- prep kernels ----------------
__global__ void prep_weights(const float* __restrict__ eWih, const float* __restrict__ eWhh,
                             const float* __restrict__ ebih, const float* __restrict__ ebhh,
                             const float* __restrict__ dWih, const float* __restrict__ dWhh,
                             const float* __restrict__ dbih, const float* __restrict__ dbhh,
                             const float* __restrict__ outW) {
    int idx = blockIdx.x * blockDim.x + threadIdx.x;
    int stride = gridDim.x * blockDim.x;
    for (int i = idx; i < 2 * G4 * KHX; i += stride) {
        int sel = i / (G4 * KHX);
        int r = i - sel * (G4 * KHX);
        int jr = r / KHX;
        int k = r - jr * KHX;
        int gate = jr & 3, col = jr >> 2;
        int js = gate * HH + col;
        const float* Wih = sel ? dWih : eWih;
        const float* Whh = sel ? dWhh : eWhh;
        float w = (k < HH) ? Whh[js * HH + k] : Wih[js * DD + (k - HH)];
        g_W[sel][jr * KHX + k] = __float2half(w);
    }
    for (int i = idx; i < 2 * G4; i += stride) {
        int sel = i >> 11;
        int jr = i & (G4 - 1);
        int gate = jr & 3, col = jr >> 2;
        int js = gate * HH + col;
        g_bias[sel][jr] = sel ? (dbih[js] + dbhh[js]) : (ebih[js] + ebhh[js]);
    }
    for (int i = idx; i < OO * HH; i += stride) {
        float w = outW[i];
        __nv_bfloat16 hi = __float2bfloat16(w);
        g_Wo_hi[i] = hi;
        g_Wo_lo[i] = __float2bfloat16(w - __bfloat162float(hi));
    }
}

__global__ void prep_x(const float* __restrict__ enc, const float* __restrict__ dec) {
    int idx = blockIdx.x * blockDim.x + threadIdx.x;
    int stride = gridDim.x * blockDim.x;
    const int total = TT * BB * DD;
    for (int i = idx; i < total; i += stride) {
        int t = i / (BB * DD);
        int r = i - t * (BB * DD);
        int b = r / DD;
        int d = r - b * DD;
        float v = (t < TENC) ? enc[(b * TENC + t) * DD + d]
                             : dec[(b * TDEC + (t - TENC)) * DD + d];
        g_x[i] = __float2half(v);
    }
}

__global__ void init_state() {
    int idx = blockIdx.x * blockDim.x + threadIdx.x;
    int stride = gridDim.x * blockDim.x;
    if (idx < 8) g_cnt[idx] = 0u;
    for (int i = idx; i < BB * HH; i += stride) {
        g_h[0][i] = __float2half(0.f);
        g_h[1][i] = __float2half(0.f);
    }
}

// ---------------- persistent LSTM kernel ----------------
// grid (16 j-blocks, 8 batch-groups) = 128 CTAs; 512 threads = 16 warps: nw4 x mw2 x kw2
// CTA tile per step: M=32 batch x N=128 gate-rows x K=576 (8 h-chunks of 64 + 1 x-chunk).
// R8 schedule; changes: (1) bias cached in 4 registers per thread (no epilogue LDG),
// (2) x(t+1) issued right after the h-wave wait instead of after the epilogue.
__global__ __launch_bounds__(512, 1) void lstm_persist(float* __restrict__ hid_base) {
    extern __shared__ __align__(16) char sm[];
    const uint32_t sbase = (uint32_t)__cvta_generic_to_shared(sm);
    const int tid = threadIdx.x;
    const int lane = tid & 31;
    const int warp = tid >> 5;
    const int nw = warp & 3;
    const int mw = (warp >> 2) & 1;
    const int kw = warp >> 3;
    const int jb = blockIdx.x;
    const int j0 = jb * 128;          // gate-row base
    const int b0 = blockIdx.y * 32;   // batch base
    const int gm = blockIdx.y;        // batch group
    const int c0 = jb * 32;           // h-column base

    auto loadW = [&](int sel) {
        for (int j = 0; j < 18; ++j) {
            int i = tid + j * 512;
            int r = i / 72, u = i - r * 72;
            cp16(sbase + r * 1168 + u * 16, g_W[sel] + (j0 + r) * KHX + u * 8);
        }
        cp_commit();
        cp_wait<0>();
        __syncthreads();
    };
    loadW(0);

    float creg[2] = {0.f, 0.f};

    const int fr = lane & 15;
    const int fhalf = (lane >> 4) * 16;

    // epilogue constants: both iterations share cl = tid & 31
    const int ecl = tid & 31;
    const int ebl0 = tid >> 5;          // rows ebl0 and ebl0+16
    float bi[4];
    auto loadBias = [&](int sel) {
#pragma unroll
        for (int g = 0; g < 4; ++g) bi[g] = g_bias[sel][j0 + ecl * 4 + g];
    };
    loadBias(0);

    auto issueX = [&](int tt) {
        if (tid < 256) {
            int r = tid >> 3, u = tid & 7;
            cp16(sbase + ABASE + 8 * ACH + r * 144 + u * 16,
                 g_x + (size_t)tt * (BB * DD) + (b0 + r) * DD + u * 8);
        }
    };
    auto issueH = [&](int p) {
#pragma unroll
        for (int j = 0; j < 4; ++j) {
            int i = tid + j * 512;
            int c = i >> 8, rem = i & 255;
            int r = rem >> 3, u = rem & 7;
            cp16(sbase + ABASE + (uint32_t)(c * ACH) + r * 144 + u * 16,
                 g_h[p] + (b0 + r) * HH + c * 64 + u * 8);
        }
    };

    auto compute = [&](int c, float (&acc)[4][4]) {
        uint32_t st = sbase + ABASE + (uint32_t)(c * ACH);
#pragma unroll
        for (int ks = 0; ks < 2; ++ks) {
            uint32_t a[4], b[8];
            ldsm4(a, st + (mw * 16 + fr) * 144 + kw * 64 + ks * 32 + fhalf);
            uint32_t kb = (uint32_t)(c * 128 + kw * 64 + ks * 32) + fhalf;
            ldsm4(b,     sbase + (nw * 32 + fr) * 1168 + kb);
            ldsm4(b + 4, sbase + (nw * 32 + 16 + fr) * 1168 + kb);
#pragma unroll
            for (int f = 0; f < 4; ++f) {
                uint32_t b0r = b[(f >> 1) * 4 + (f & 1)];
                uint32_t b1r = b[(f >> 1) * 4 + 2 + (f & 1)];
                mma_f16(acc[f], a[0], a[1], a[2], a[3], b0r, b1r);
            }
        }
    };

    float acc[4][4];

    // prefetch x chunk for t=0
    issueX(0);
    cp_commit();

    for (int t = 0; t < TT; ++t) {
        const int p = t & 1;

        // ---- group barrier: all 16 producers published h of step t-1 ----
        if (t > 0) {
            if (tid == 0) {
                const unsigned target = 16u * (unsigned)t;
                unsigned v;
                do {
                    asm volatile("ld.acquire.gpu.global.u32 %0, [%1];"
                                 : "=r"(v) : "l"(&g_cnt[gm]));
                } while (v < target);
            }
            __syncthreads();
        }
        if (t == TENC) { loadW(1); loadBias(1); }

        // ---- issue full h wave (one group) ----
        issueH(p);
        cp_commit();

#pragma unroll
        for (int f = 0; f < 4; ++f)
#pragma unroll
            for (int e = 0; e < 4; ++e) acc[f][e] = 0.f;

        // ---- compute x chunk while h flies ----
        cp_wait<1>();
        __syncthreads();
        compute(8, acc);

        cp_wait<0>();
        __syncthreads();

        // x(t+1) slot is free (compute(8) done by all warps) — issue early
        if (t + 1 < TT) { issueX(t + 1); cp_commit(); }

#pragma unroll
        for (int c = 0; c < 8; ++c) compute(c, acc);

        // ---- single-round kw reduction: kw0 -> zA, kw1 -> zB concurrently ----
        float* zA = (float*)(sm + ZOFS);
        float* zB = zA + 4224;
        float* zt = kw ? zB : zA;
#pragma unroll
        for (int f = 0; f < 4; ++f) {
            int zr = mw * 16 + (lane >> 2);
            int zc = nw * 32 + f * 8 + (lane & 3) * 2;
            zt[zr * 132 + zc]           = acc[f][0];
            zt[zr * 132 + zc + 1]       = acc[f][1];
            zt[(zr + 8) * 132 + zc]     = acc[f][2];
            zt[(zr + 8) * 132 + zc + 1] = acc[f][3];
        }
        __syncthreads();

        // ---- LSTM cell epilogue (c and bias in registers) ----
        const int wp = p ^ 1;
        float hN2[2];
#pragma unroll
        for (int it = 0; it < 2; ++it) {
            int bl_ = ebl0 + it * 16;
            float zi = zA[bl_ * 132 + ecl * 4 + 0] + zB[bl_ * 132 + ecl * 4 + 0] + bi[0];
            float zf = zA[bl_ * 132 + ecl * 4 + 1] + zB[bl_ * 132 + ecl * 4 + 1] + bi[1];
            float zg = zA[bl_ * 132 + ecl * 4 + 2] + zB[bl_ * 132 + ecl * 4 + 2] + bi[2];
            float zo = zA[bl_ * 132 + ecl * 4 + 3] + zB[bl_ * 132 + ecl * 4 + 3] + bi[3];
            float ig = sigmoidf_(zi);
            float fg = sigmoidf_(zf);
            float gg = tanhf_(zg);
            float og = sigmoidf_(zo);
            float cN = fg * creg[it] + ig * gg;
            float hN = og * tanhf_(cN);
            creg[it] = cN;
            hN2[it] = hN;
            g_h[wp][(b0 + bl_) * HH + c0 + ecl] = __float2half(hN);
        }
        __syncthreads();   // all h stores done before the release arrival

        if (t + 1 < TT && tid == 0) {
            asm volatile("red.release.gpu.global.add.u32 [%0], %1;"
                         :: "l"(&g_cnt[gm]), "r"(1u) : "memory");
        }
        if (t >= TENC) {
#pragma unroll
            for (int it = 0; it < 2; ++it) {
                int bl_ = ebl0 + it * 16;
                hid_base[(size_t)(b0 + bl_) * (TDEC * HH) + (t - TENC) * HH + c0 + ecl] = hN2[it];
            }
        }
    }
}

// ---------------- final output projection (bf16 3-term) ----------------
struct STiles {
    __nv_bfloat16 Ah[2][32][36];
    __nv_bfloat16 Al[2][32][36];
    __nv_bfloat16 Bh[2][128][36];
    __nv_bfloat16 Bl[2][128][36];
};
union SU {
    STiles t;
    float z[32][132];
};

__global__ __launch_bounds__(256) void proj_kernel(const float* __restrict__ hid,
                                                   const float* __restrict__ outb,
                                                   float* __restrict__ out) {
    __shared__ SU su;
    const int tid = threadIdx.x;
    const int lane = tid & 31;
    const int warp = tid >> 5;
    const int wm = (warp & 1) * 16;
    const int wn = (warp >> 1) * 32;
    const int m0 = blockIdx.y * 32;
    const int n0 = blockIdx.x * 128;

    float acc[4][4];
#pragma unroll
    for (int s = 0; s < 4; ++s)
#pragma unroll
        for (int i = 0; i < 4; ++i) acc[s][i] = 0.f;

#pragma unroll
    for (int j = 0; j < 4; ++j) {
        int i = tid + j * 256;
        int row = i >> 5, k = i & 31;
        float v = hid[(m0 + row) * HH + k];
        __nv_bfloat16 hi = __float2bfloat16(v);
        su.t.Ah[0][row][k] = hi;
        su.t.Al[0][row][k] = __float2bfloat16(v - __bfloat162float(hi));
    }
#pragma unroll
    for (int j = 0; j < 8; ++j) {
        int i = tid + j * 256;
        int row = i >> 4, k2 = (i & 15) * 2;
        int off = (n0 + row) * HH + k2;
        *(uint32_t*)&su.t.Bh[0][row][k2] = *(const uint32_t*)(g_Wo_hi + off);
        *(uint32_t*)&su.t.Bl[0][row][k2] = *(const uint32_t*)(g_Wo_lo + off);
    }

    float pv[4];
    uint32_t pBh[8], pBl[8];
    const int NCHP = HH / 32;

    for (int kc = 0; kc < NCHP; ++kc) {
        __syncthreads();
        const int q = kc & 1;
        if (kc + 1 < NCHP) {
            const int kn = kc + 1;
#pragma unroll
            for (int j = 0; j < 4; ++j) {
                int i = tid + j * 256;
                int row = i >> 5, k = i & 31;
                pv[j] = hid[(m0 + row) * HH + kn * 32 + k];
            }
#pragma unroll
            for (int j = 0; j < 8; ++j) {
                int i = tid + j * 256;
                int row = i >> 4, k2 = (i & 15) * 2;
                int off = (n0 + row) * HH + kn * 32 + k2;
                pBh[j] = *(const uint32_t*)(g_Wo_hi + off);
                pBl[j] = *(const uint32_t*)(g_Wo_lo + off);
            }
        }
#pragma unroll
        for (int k16 = 0; k16 < 2; ++k16) {
            const int ar = wm + (lane >> 2);
            const int ac = (lane & 3) * 2 + k16 * 16;
            uint32_t ah0 = *(const uint32_t*)&su.t.Ah[q][ar][ac];
            uint32_t ah1 = *(const uint32_t*)&su.t.Ah[q][ar + 8][ac];
            uint32_t ah2 = *(const uint32_t*)&su.t.Ah[q][ar][ac + 8];
            uint32_t ah3 = *(const uint32_t*)&su.t.Ah[q][ar + 8][ac + 8];
            uint32_t al0 = *(const uint32_t*)&su.t.Al[q][ar][ac];
            uint32_t al1 = *(const uint32_t*)&su.t.Al[q][ar + 8][ac];
            uint32_t al2 = *(const uint32_t*)&su.t.Al[q][ar][ac + 8];
            uint32_t al3 = *(const uint32_t*)&su.t.Al[q][ar + 8][ac + 8];
#pragma unroll
            for (int s = 0; s < 4; ++s) {
                const int br = wn + s * 8 + (lane >> 2);
                const int bc = (lane & 3) * 2 + k16 * 16;
                uint32_t bh0 = *(const uint32_t*)&su.t.Bh[q][br][bc];
                uint32_t bh1 = *(const uint32_t*)&su.t.Bh[q][br][bc + 8];
                uint32_t bl0 = *(const uint32_t*)&su.t.Bl[q][br][bc];
                uint32_t bl1 = *(const uint32_t*)&su.t.Bl[q][br][bc + 8];
                mma_bf16(acc[s], ah0, ah1, ah2, ah3, bh0, bh1);
                mma_bf16(acc[s], ah0, ah1, ah2, ah3, bl0, bl1);
                mma_bf16(acc[s], al0, al1, al2, al3, bh0, bh1);
            }
        }
        if (kc + 1 < NCHP) {
            const int qn = q ^ 1;
#pragma unroll
            for (int j = 0; j < 4; ++j) {
                int i = tid + j * 256;
                int row = i >> 5, k = i & 31;
                __nv_bfloat16 hi = __float2bfloat16(pv[j]);
                su.t.Ah[qn][row][k] = hi;
                su.t.Al[qn][row][k] = __float2bfloat16(pv[j] - __bfloat162float(hi));
            }
#pragma unroll
            for (int j = 0; j < 8; ++j) {
                int i = tid + j * 256;
                int row = i >> 4, k2 = (i & 15) * 2;
                *(uint32_t*)&su.t.Bh[qn][row][k2] = pBh[j];
                *(uint32_t*)&su.t.Bl[qn][row][k2] = pBl[j];
            }
        }
    }

#pragma unroll
    for (int s = 0; s < 4; ++s) {
        const int r = m0 + wm + (lane >> 2);
        const int cc = n0 + wn + s * 8 + (lane & 3) * 2;
        out[(size_t)r * OO + cc]           = acc[s][0] + outb[cc];
        out[(size_t)r * OO + cc + 1]       = acc[s][1] + outb[cc + 1];
        out[(size_t)(r + 8) * OO + cc]     = acc[s][2] + outb[cc];
        out[(size_t)(r + 8) * OO + cc + 1] = acc[s][3] + outb[cc + 1];
    }
}

// ---------------- launch ----------------
extern "C" void kernel_launch(void* const* d_in, const int* in_sizes, int n_in,
                              void* d_out, int out_size) {
    const float* enc_inp = (const float*)d_in[0];
    const float* dec_inp = (const float*)d_in[1];
    const float* eWih = (const float*)d_in[2];
    const float* eWhh = (const float*)d_in[3];
    const float* ebih = (const float*)d_in[4];
    const float* ebhh = (const float*)d_in[5];
    const float* dWih = (const float*)d_in[6];
    const float* dWhh = (const float*)d_in[7];
    const float* dbih = (const float*)d_in[8];
    const float* dbhh = (const float*)d_in[9];
    const float* outW = (const float*)d_in[10];
    const float* outb = (const float*)d_in[11];
    float* out = (float*)d_out;

    static int configured = 0;
    if (!configured) {
        cudaFuncSetAttribute(lstm_persist, cudaFuncAttributeMaxDynamicSharedMemorySize,
                             SMEM_DYN);
        configured = 1;
    }

    prep_weights<<<256, 256>>>(eWih, eWhh, ebih, ebhh, dWih, dWhh, dbih, dbhh, outW);
    prep_x<<<2048, 256>>>(enc_inp, dec_inp);
    init_state<<<512, 256>>>();

    float* hid_base = out + OUT_OFS;
    lstm_persist<<<dim3(16, 8), 512, SMEM_DYN>>>(hid_base);
    proj_kernel<<<dim3(4, 512), 256>>>(hid_base, outb, out);
}

// round 16
// speedup vs baseline: 1.5883x; 1.0120x over previous
#include <cuda_runtime.h>
#include <cuda_bf16.h>
#include <cuda_fp16.h>
#include <cstdint>

#define BB 256
#define TENC 512
#define TDEC 64
#define TT (TENC + TDEC)
#define DD 64
#define HH 512
#define OO 512
#define G4 2048            // 4*H
#define KHX 576            // H + D
#define OUT_OFS ((size_t)BB * TDEC * OO)

// smem layout (dynamic), bytes:
//  W @ 0          : 128 rows x 1168 B = 149504
//  A chunks @ 149504 : 9 x 4608 (32 rows x 144B)  -> 190976
//  zA @ 190976 (32x132 f32 = 16896); zB @ 207872 -> 224768
#define ABASE   149504u
#define ACH     4608u
#define ZOFS    190976u
#define SMEM_DYN 224768

// ---------------- device-global scratch ----------------
__device__ __align__(16) __half g_W[2][G4 * KHX];
__device__ __align__(16) float  g_bias[2][G4];
__device__ __align__(16) __half g_x[TT * BB * DD];
__device__ __align__(16) __half g_h[2][BB * HH];
__device__ __align__(16) __nv_bfloat16 g_Wo_hi[OO * HH];
__device__ __align__(16) __nv_bfloat16 g_Wo_lo[OO * HH];
__device__ unsigned g_cnt[8];   // per batch-group arrival counter

// ---------------- helpers ----------------
__device__ __forceinline__ void mma_f16(float (&c)[4],
                                        uint32_t a0, uint32_t a1, uint32_t a2, uint32_t a3,
                                        uint32_t b0, uint32_t b1) {
    asm volatile(
        "mma.sync.aligned.m16n8k16.row.col.f32.f16.f16.f32 "
        "{%0,%1,%2,%3}, {%4,%5,%6,%7}, {%8,%9}, {%0,%1,%2,%3};\n"
        : "+f"(c[0]), "+f"(c[1]), "+f"(c[2]), "+f"(c[3])
        : "r"(a0), "r"(a1), "r"(a2), "r"(a3), "r"(b0), "r"(b1));
}

__device__ __forceinline__ void mma_bf16(float (&c)[4],
                                         uint32_t a0, uint32_t a1, uint32_t a2, uint32_t a3,
                                         uint32_t b0, uint32_t b1) {
    asm volatile(
        "mma.sync.aligned.m16n8k16.row.col.f32.bf16.bf16.f32 "
        "{%0,%1,%2,%3}, {%4,%5,%6,%7}, {%8,%9}, {%0,%1,%2,%3};\n"
        : "+f"(c[0]), "+f"(c[1]), "+f"(c[2]), "+f"(c[3])
        : "r"(a0), "r"(a1), "r"(a2), "r"(a3), "r"(b0), "r"(b1));
}

__device__ __forceinline__ void ldsm4(uint32_t* r, uint32_t addr) {
    asm volatile("ldmatrix.sync.aligned.m8n8.x4.shared.b16 {%0,%1,%2,%3}, [%4];\n"
                 : "=r"(r[0]), "=r"(r[1]), "=r"(r[2]), "=r"(r[3]) : "r"(addr));
}

__device__ __forceinline__ void cp16(uint32_t dst, const void* src) {
    asm volatile("cp.async.cg.shared.global [%0], [%1], 16;\n" :: "r"(dst), "l"(src));
}
__device__ __forceinline__ void cp_commit() { asm volatile("cp.async.commit_group;\n"); }
template <int N> __device__ __forceinline__ void cp_wait() {
    asm volatile("cp.async.wait_group %0;\n" :: "n"(N));
}

__device__ __forceinline__ float sigmoidf_(float x) { return 1.f / (1.f + __expf(-x)); }
__device__ __forceinline__ float tanhf_(float x) { return 1.f - 2.f / (__expf(2.f * x) + 1.f); }

// ---------------- prep kernels ----------------
__global__ void prep_weights(const float* __restrict__ eWih, const float* __restrict__ eWhh,
                             const float* __restrict__ ebih, const float* __restrict__ ebhh,
                             const float* __restrict__ dWih, const float* __restrict__ dWhh,
                             const float* __restrict__ dbih, const float* __restrict__ dbhh,
                             const float* __restrict__ outW) {
    int idx = blockIdx.x * blockDim.x + threadIdx.x;
    int stride = gridDim.x * blockDim.x;
    for (int i = idx; i < 2 * G4 * KHX; i += stride) {
        int sel = i / (G4 * KHX);
        int r = i - sel * (G4 * KHX);
        int jr = r / KHX;
        int k = r - jr * KHX;
        int gate = jr & 3, col = jr >> 2;
        int js = gate * HH + col;
        const float* Wih = sel ? dWih : eWih;
        const float* Whh = sel ? dWhh : eWhh;
        float w = (k < HH) ? Whh[js * HH + k] : Wih[js * DD + (k - HH)];
        g_W[sel][jr * KHX + k] = __float2half(w);
    }
    for (int i = idx; i < 2 * G4; i += stride) {
        int sel = i >> 11;
        int jr = i & (G4 - 1);
        int gate = jr & 3, col = jr >> 2;
        int js = gate * HH + col;
        g_bias[sel][jr] = sel ? (dbih[js] + dbhh[js]) : (ebih[js] + ebhh[js]);
    }
    for (int i = idx; i < OO * HH; i += stride) {
        float w = outW[i];
        __nv_bfloat16 hi = __float2bfloat16(w);
        g_Wo_hi[i] = hi;
        g_Wo_lo[i] = __float2bfloat16(w - __bfloat162float(hi));
    }
}

__global__ void prep_x(const float* __restrict__ enc, const float* __restrict__ dec) {
    int idx = blockIdx.x * blockDim.x + threadIdx.x;
    int stride = gridDim.x * blockDim.x;
    const int total = TT * BB * DD;
    for (int i = idx; i < total; i += stride) {
        int t = i / (BB * DD);
        int r = i - t * (BB * DD);
        int b = r / DD;
        int d = r - b * DD;
        float v = (t < TENC) ? enc[(b * TENC + t) * DD + d]
                             : dec[(b * TDEC + (t - TENC)) * DD + d];
        g_x[i] = __float2half(v);
    }
}

__global__ void init_state() {
    int idx = blockIdx.x * blockDim.x + threadIdx.x;
    int stride = gridDim.x * blockDim.x;
    if (idx < 8) g_cnt[idx] = 0u;
    for (int i = idx; i < BB * HH; i += stride) {
        g_h[0][i] = __float2half(0.f);
        g_h[1][i] = __float2half(0.f);
    }
}

// ---------------- persistent LSTM kernel ----------------
// grid (16 j-blocks, 8 batch-groups) = 128 CTAs; 512 threads = 16 warps: nw4 x mw2 x kw2
// CTA tile per step: M=32 batch x N=128 gate-rows x K=576 (8 h-chunks of 64 + 1 x-chunk).
// R15 schedule; ONLY change: the x-chunk compute is hoisted ABOVE the barrier poll,
// filling the producer-straggler wait with useful work (x has ~2.5us of flight by then).
__global__ __launch_bounds__(512, 1) void lstm_persist(float* __restrict__ hid_base) {
    extern __shared__ __align__(16) char sm[];
    const uint32_t sbase = (uint32_t)__cvta_generic_to_shared(sm);
    const int tid = threadIdx.x;
    const int lane = tid & 31;
    const int warp = tid >> 5;
    const int nw = warp & 3;
    const int mw = (warp >> 2) & 1;
    const int kw = warp >> 3;
    const int jb = blockIdx.x;
    const int j0 = jb * 128;          // gate-row base
    const int b0 = blockIdx.y * 32;   // batch base
    const int gm = blockIdx.y;        // batch group
    const int c0 = jb * 32;           // h-column base

    auto loadW = [&](int sel) {
        for (int j = 0; j < 18; ++j) {
            int i = tid + j * 512;
            int r = i / 72, u = i - r * 72;
            cp16(sbase + r * 1168 + u * 16, g_W[sel] + (j0 + r) * KHX + u * 8);
        }
        cp_commit();
        cp_wait<0>();
        __syncthreads();
    };
    loadW(0);

    float creg[2] = {0.f, 0.f};

    const int fr = lane & 15;
    const int fhalf = (lane >> 4) * 16;

    // epilogue constants: both iterations share cl = tid & 31
    const int ecl = tid & 31;
    const int ebl0 = tid >> 5;          // rows ebl0 and ebl0+16
    float bi[4];
    auto loadBias = [&](int sel) {
#pragma unroll
        for (int g = 0; g < 4; ++g) bi[g] = g_bias[sel][j0 + ecl * 4 + g];
    };
    loadBias(0);

    auto issueX = [&](int tt) {
        if (tid < 256) {
            int r = tid >> 3, u = tid & 7;
            cp16(sbase + ABASE + 8 * ACH + r * 144 + u * 16,
                 g_x + (size_t)tt * (BB * DD) + (b0 + r) * DD + u * 8);
        }
    };
    auto issueH = [&](int p) {
#pragma unroll
        for (int j = 0; j < 4; ++j) {
            int i = tid + j * 512;
            int c = i >> 8, rem = i & 255;
            int r = rem >> 3, u = rem & 7;
            cp16(sbase + ABASE + (uint32_t)(c * ACH) + r * 144 + u * 16,
                 g_h[p] + (b0 + r) * HH + c * 64 + u * 8);
        }
    };

    auto compute = [&](int c, float (&acc)[4][4]) {
        uint32_t st = sbase + ABASE + (uint32_t)(c * ACH);
#pragma unroll
        for (int ks = 0; ks < 2; ++ks) {
            uint32_t a[4], b[8];
            ldsm4(a, st + (mw * 16 + fr) * 144 + kw * 64 + ks * 32 + fhalf);
            uint32_t kb = (uint32_t)(c * 128 + kw * 64 + ks * 32) + fhalf;
            ldsm4(b,     sbase + (nw * 32 + fr) * 1168 + kb);
            ldsm4(b + 4, sbase + (nw * 32 + 16 + fr) * 1168 + kb);
#pragma unroll
            for (int f = 0; f < 4; ++f) {
                uint32_t b0r = b[(f >> 1) * 4 + (f & 1)];
                uint32_t b1r = b[(f >> 1) * 4 + 2 + (f & 1)];
                mma_f16(acc[f], a[0], a[1], a[2], a[3], b0r, b1r);
            }
        }
    };

    float acc[4][4];

    // prefetch x chunk for t=0
    issueX(0);
    cp_commit();

    for (int t = 0; t < TT; ++t) {
        const int p = t & 1;

        // decoder weights must be loaded BEFORE the x-chunk compute of step TENC
        if (t == TENC) { loadW(1); loadBias(1); }

#pragma unroll
        for (int f = 0; f < 4; ++f)
#pragma unroll
            for (int e = 0; e < 4; ++e) acc[f][e] = 0.f;

        // ---- compute x chunk BEFORE the barrier (fills the straggler wait) ----
        cp_wait<0>();
        __syncthreads();
        compute(8, acc);

        // ---- group barrier: all 16 producers published h of step t-1 ----
        if (t > 0) {
            if (tid == 0) {
                const unsigned target = 16u * (unsigned)t;
                unsigned v;
                do {
                    asm volatile("ld.acquire.gpu.global.u32 %0, [%1];"
                                 : "=r"(v) : "l"(&g_cnt[gm]));
                } while (v < target);
            }
            __syncthreads();
        }

        // ---- issue full h wave (one group) ----
        issueH(p);
        cp_commit();

        cp_wait<0>();
        __syncthreads();

        // x(t+1) slot is free (compute(8) done by all warps, two syncs ago) — issue early
        if (t + 1 < TT) { issueX(t + 1); cp_commit(); }

#pragma unroll
        for (int c = 0; c < 8; ++c) compute(c, acc);

        // ---- single-round kw reduction: kw0 -> zA, kw1 -> zB concurrently ----
        float* zA = (float*)(sm + ZOFS);
        float* zB = zA + 4224;
        float* zt = kw ? zB : zA;
#pragma unroll
        for (int f = 0; f < 4; ++f) {
            int zr = mw * 16 + (lane >> 2);
            int zc = nw * 32 + f * 8 + (lane & 3) * 2;
            zt[zr * 132 + zc]           = acc[f][0];
            zt[zr * 132 + zc + 1]       = acc[f][1];
            zt[(zr + 8) * 132 + zc]     = acc[f][2];
            zt[(zr + 8) * 132 + zc + 1] = acc[f][3];
        }
        __syncthreads();

        // ---- LSTM cell epilogue (c and bias in registers) ----
        const int wp = p ^ 1;
        float hN2[2];
#pragma unroll
        for (int it = 0; it < 2; ++it) {
            int bl_ = ebl0 + it * 16;
            float zi = zA[bl_ * 132 + ecl * 4 + 0] + zB[bl_ * 132 + ecl * 4 + 0] + bi[0];
            float zf = zA[bl_ * 132 + ecl * 4 + 1] + zB[bl_ * 132 + ecl * 4 + 1] + bi[1];
            float zg = zA[bl_ * 132 + ecl * 4 + 2] + zB[bl_ * 132 + ecl * 4 + 2] + bi[2];
            float zo = zA[bl_ * 132 + ecl * 4 + 3] + zB[bl_ * 132 + ecl * 4 + 3] + bi[3];
            float ig = sigmoidf_(zi);
            float fg = sigmoidf_(zf);
            float gg = tanhf_(zg);
            float og = sigmoidf_(zo);
            float cN = fg * creg[it] + ig * gg;
            float hN = og * tanhf_(cN);
            creg[it] = cN;
            hN2[it] = hN;
            g_h[wp][(b0 + bl_) * HH + c0 + ecl] = __float2half(hN);
        }
        __syncthreads();   // all h stores done before the release arrival

        if (t + 1 < TT && tid == 0) {
            asm volatile("red.release.gpu.global.add.u32 [%0], %1;"
                         :: "l"(&g_cnt[gm]), "r"(1u) : "memory");
        }
        if (t >= TENC) {
#pragma unroll
            for (int it = 0; it < 2; ++it) {
                int bl_ = ebl0 + it * 16;
                hid_base[(size_t)(b0 + bl_) * (TDEC * HH) + (t - TENC) * HH + c0 + ecl] = hN2[it];
            }
        }
    }
}

// ---------------- final output projection (bf16 3-term) ----------------
struct STiles {
    __nv_bfloat16 Ah[2][32][36];
    __nv_bfloat16 Al[2][32][36];
    __nv_bfloat16 Bh[2][128][36];
    __nv_bfloat16 Bl[2][128][36];
};
union SU {
    STiles t;
    float z[32][132];
};

__global__ __launch_bounds__(256) void proj_kernel(const float* __restrict__ hid,
                                                   const float* __restrict__ outb,
                                                   float* __restrict__ out) {
    __shared__ SU su;
    const int tid = threadIdx.x;
    const int lane = tid & 31;
    const int warp = tid >> 5;
    const int wm = (warp & 1) * 16;
    const int wn = (warp >> 1) * 32;
    const int m0 = blockIdx.y * 32;
    const int n0 = blockIdx.x * 128;

    float acc[4][4];
#pragma unroll
    for (int s = 0; s < 4; ++s)
#pragma unroll
        for (int i = 0; i < 4; ++i) acc[s][i] = 0.f;

#pragma unroll
    for (int j = 0; j < 4; ++j) {
        int i = tid + j * 256;
        int row = i >> 5, k = i & 31;
        float v = hid[(m0 + row) * HH + k];
        __nv_bfloat16 hi = __float2bfloat16(v);
        su.t.Ah[0][row][k] = hi;
        su.t.Al[0][row][k] = __float2bfloat16(v - __bfloat162float(hi));
    }
#pragma unroll
    for (int j = 0; j < 8; ++j) {
        int i = tid + j * 256;
        int row = i >> 4, k2 = (i & 15) * 2;
        int off = (n0 + row) * HH + k2;
        *(uint32_t*)&su.t.Bh[0][row][k2] = *(const uint32_t*)(g_Wo_hi + off);
        *(uint32_t*)&su.t.Bl[0][row][k2] = *(const uint32_t*)(g_Wo_lo + off);
    }

    float pv[4];
    uint32_t pBh[8], pBl[8];
    const int NCHP = HH / 32;

    for (int kc = 0; kc < NCHP; ++kc) {
        __syncthreads();
        const int q = kc & 1;
        if (kc + 1 < NCHP) {
            const int kn = kc + 1;
#pragma unroll
            for (int j = 0; j < 4; ++j) {
                int i = tid + j * 256;
                int row = i >> 5, k = i & 31;
                pv[j] = hid[(m0 + row) * HH + kn * 32 + k];
            }
#pragma unroll
            for (int j = 0; j < 8; ++j) {
                int i = tid + j * 256;
                int row = i >> 4, k2 = (i & 15) * 2;
                int off = (n0 + row) * HH + kn * 32 + k2;
                pBh[j] = *(const uint32_t*)(g_Wo_hi + off);
                pBl[j] = *(const uint32_t*)(g_Wo_lo + off);
            }
        }
#pragma unroll
        for (int k16 = 0; k16 < 2; ++k16) {
            const int ar = wm + (lane >> 2);
            const int ac = (lane & 3) * 2 + k16 * 16;
            uint32_t ah0 = *(const uint32_t*)&su.t.Ah[q][ar][ac];
            uint32_t ah1 = *(const uint32_t*)&su.t.Ah[q][ar + 8][ac];
            uint32_t ah2 = *(const uint32_t*)&su.t.Ah[q][ar][ac + 8];
            uint32_t ah3 = *(const uint32_t*)&su.t.Ah[q][ar + 8][ac + 8];
            uint32_t al0 = *(const uint32_t*)&su.t.Al[q][ar][ac];
            uint32_t al1 = *(const uint32_t*)&su.t.Al[q][ar + 8][ac];
            uint32_t al2 = *(const uint32_t*)&su.t.Al[q][ar][ac + 8];
            uint32_t al3 = *(const uint32_t*)&su.t.Al[q][ar + 8][ac + 8];
#pragma unroll
            for (int s = 0; s < 4; ++s) {
                const int br = wn + s * 8 + (lane >> 2);
                const int bc = (lane & 3) * 2 + k16 * 16;
                uint32_t bh0 = *(const uint32_t*)&su.t.Bh[q][br][bc];
                uint32_t bh1 = *(const uint32_t*)&su.t.Bh[q][br][bc + 8];
                uint32_t bl0 = *(const uint32_t*)&su.t.Bl[q][br][bc];
                uint32_t bl1 = *(const uint32_t*)&su.t.Bl[q][br][bc + 8];
                mma_bf16(acc[s], ah0, ah1, ah2, ah3, bh0, bh1);
                mma_bf16(acc[s], ah0, ah1, ah2, ah3, bl0, bl1);
                mma_bf16(acc[s], al0, al1, al2, al3, bh0, bh1);
            }
        }
        if (kc + 1 < NCHP) {
            const int qn = q ^ 1;
#pragma unroll
            for (int j = 0; j < 4; ++j) {
                int i = tid + j * 256;
                int row = i >> 5, k = i & 31;
                __nv_bfloat16 hi = __float2bfloat16(pv[j]);
                su.t.Ah[qn][row][k] = hi;
                su.t.Al[qn][row][k] = __float2bfloat16(pv[j] - __bfloat162float(hi));
            }
#pragma unroll
            for (int j = 0; j < 8; ++j) {
                int i = tid + j * 256;
                int row = i >> 4, k2 = (i & 15) * 2;
                *(uint32_t*)&su.t.Bh[qn][row][k2] = pBh[j];
                *(uint32_t*)&su.t.Bl[qn][row][k2] = pBl[j];
            }
        }
    }

#pragma unroll
    for (int s = 0; s < 4; ++s) {
        const int r = m0 + wm + (lane >> 2);
        const int cc = n0 + wn + s * 8 + (lane & 3) * 2;
        out[(size_t)r * OO + cc]           = acc[s][0] + outb[cc];
        out[(size_t)r * OO + cc + 1]       = acc[s][1] + outb[cc + 1];
        out[(size_t)(r + 8) * OO + cc]     = acc[s][2] + outb[cc];
        out[(size_t)(r + 8) * OO + cc + 1] = acc[s][3] + outb[cc + 1];
    }
}

// ---------------- launch ----------------
extern "C" void kernel_launch(void* const* d_in, const int* in_sizes, int n_in,
                              void* d_out, int out_size) {
    const float* enc_inp = (const float*)d_in[0];
    const float* dec_inp = (const float*)d_in[1];
    const float* eWih = (const float*)d_in[2];
    const float* eWhh = (const float*)d_in[3];
    const float* ebih = (const float*)d_in[4];
    const float* ebhh = (const float*)d_in[5];
    const float* dWih = (const float*)d_in[6];
    const float* dWhh = (const float*)d_in[7];
    const float* dbih = (const float*)d_in[8];
    const float* dbhh = (const float*)d_in[9];
    const float* outW = (const float*)d_in[10];
    const float* outb = (const float*)d_in[11];
    float* out = (float*)d_out;

    static int configured = 0;
    if (!configured) {
        cudaFuncSetAttribute(lstm_persist, cudaFuncAttributeMaxDynamicSharedMemorySize,
                             SMEM_DYN);
        configured = 1;
    }

    prep_weights<<<256, 256>>>(eWih, eWhh, ebih, ebhh, dWih, dWhh, dbih, dbhh, outW);
    prep_x<<<2048, 256>>>(enc_inp, dec_inp);
    init_state<<<512, 256>>>();

    float* hid_base = out + OUT_OFS;
    lstm_persist<<<dim3(16, 8), 512, SMEM_DYN>>>(hid_base);
    proj_kernel<<<dim3(4, 512), 256>>>(hid_base, outb, out);
}